// round 1
// baseline (speedup 1.0000x reference)
#include <cuda_runtime.h>
#include <float.h>

// ---------------------------------------------------------------------------
// Problem constants
// ---------------------------------------------------------------------------
#define Bn     16
#define Hn     16
#define DHn    64
#define NTOK   1280          // padded sequence (SEQ_LEN + 1)
#define NREAL  1279          // real tokens
#define DIMn   1024
#define TXT    256           // text length
#define BH     256           // Bn * Hn
#define HD     (NTOK * DHn)  // 81920 floats per (b,h) plane
#define MQKV   (Bn * NTOK)   // 20480
#define MOUT   (Bn * NREAL)  // 20464
#define QSCALE 0.125f        // DH^-0.5

// Attention smem layout (floats): Qs[32][68], KV[64][68], S[32][292]
#define QS_STRIDE 68
#define S_STRIDE  292
#define SM_QS 0
#define SM_KV (32 * QS_STRIDE)
#define SM_S  (32 * QS_STRIDE + 64 * QS_STRIDE)
#define SMEM_ATTN_BYTES ((32 * QS_STRIDE + 64 * QS_STRIDE + 32 * S_STRIDE) * 4)

// ---------------------------------------------------------------------------
// Scratch (device globals: allocation-free)
// ---------------------------------------------------------------------------
__device__ float g_q[BH * HD];
__device__ float g_k[BH * HD];
__device__ float g_v[BH * HD];
__device__ float g_o[BH * HD];

// ---------------------------------------------------------------------------
// Kernel 1: fused QKV projection.
// C[m, j] = sum_k xp[m,k] * w_qkv[j,k];   m = b*1280 + n (n==1279 -> zero row)
// j in [0,3072): 0..1023 -> Q (scaled), 1024..2047 -> K, 2048..3071 -> V.
// Written directly in (b*H+h, n, d) head layout.
// 128x128x8 tile, 256 threads, 8x8 per thread, reg prefetch.
// ---------------------------------------------------------------------------
__global__ __launch_bounds__(256) void qkv_gemm_kernel(
    const float* __restrict__ X, const float* __restrict__ W)
{
    __shared__ __align__(16) float As[8][128];
    __shared__ __align__(16) float Bs[8][128];

    const int m0  = blockIdx.y * 128;
    const int n0  = blockIdx.x * 128;
    const int tid = threadIdx.x;
    const int tx  = tid & 15;
    const int ty  = tid >> 4;
    const int lrow = tid >> 1;
    const int lcol = (tid & 1) * 4;

    const int am = m0 + lrow;
    const int ab = am / NTOK;
    const int an = am - ab * NTOK;
    const bool avalid = (an < NREAL);
    const float* aptr = X + ((size_t)ab * NREAL + an) * DIMn;
    const float* bptr = W + (size_t)(n0 + lrow) * DIMn;

    float acc[8][8];
#pragma unroll
    for (int i = 0; i < 8; i++)
#pragma unroll
        for (int j = 0; j < 8; j++) acc[i][j] = 0.f;

    float4 af = avalid ? *(const float4*)(aptr + lcol) : make_float4(0.f, 0.f, 0.f, 0.f);
    float4 bf = *(const float4*)(bptr + lcol);

    for (int k0 = 0; k0 < DIMn; k0 += 8) {
        __syncthreads();
        As[lcol + 0][lrow] = af.x; As[lcol + 1][lrow] = af.y;
        As[lcol + 2][lrow] = af.z; As[lcol + 3][lrow] = af.w;
        Bs[lcol + 0][lrow] = bf.x; Bs[lcol + 1][lrow] = bf.y;
        Bs[lcol + 2][lrow] = bf.z; Bs[lcol + 3][lrow] = bf.w;
        __syncthreads();
        if (k0 + 8 < DIMn) {
            af = avalid ? *(const float4*)(aptr + k0 + 8 + lcol)
                        : make_float4(0.f, 0.f, 0.f, 0.f);
            bf = *(const float4*)(bptr + k0 + 8 + lcol);
        }
#pragma unroll
        for (int kk = 0; kk < 8; kk++) {
            float4 a0 = *(const float4*)&As[kk][ty * 4];
            float4 a1 = *(const float4*)&As[kk][64 + ty * 4];
            float4 b0 = *(const float4*)&Bs[kk][tx * 4];
            float4 b1 = *(const float4*)&Bs[kk][64 + tx * 4];
            float av[8] = {a0.x, a0.y, a0.z, a0.w, a1.x, a1.y, a1.z, a1.w};
            float bv[8] = {b0.x, b0.y, b0.z, b0.w, b1.x, b1.y, b1.z, b1.w};
#pragma unroll
            for (int i = 0; i < 8; i++)
#pragma unroll
                for (int j = 0; j < 8; j++) acc[i][j] += av[i] * bv[j];
        }
    }

    // Epilogue: scatter into g_q / g_k / g_v with head layout, scale Q.
#pragma unroll
    for (int i = 0; i < 8; i++) {
        const int mrow = m0 + ((i < 4) ? (ty * 4 + i) : (64 + ty * 4 + i - 4));
        const int b = mrow / NTOK;
        const int n = mrow - b * NTOK;
#pragma unroll
        for (int jg = 0; jg < 2; jg++) {
            const int col = n0 + ((jg == 0) ? (tx * 4) : (64 + tx * 4));
            const int which = col >> 10;        // 0=q 1=k 2=v
            const int cc = col & 1023;
            const int h = cc >> 6;
            const int d = cc & 63;
            float* dst = (which == 0) ? g_q : ((which == 1) ? g_k : g_v);
            const float sc = (which == 0) ? QSCALE : 1.0f;
            float4 v;
            v.x = acc[i][jg * 4 + 0] * sc;
            v.y = acc[i][jg * 4 + 1] * sc;
            v.z = acc[i][jg * 4 + 2] * sc;
            v.w = acc[i][jg * 4 + 3] * sc;
            *(float4*)(dst + ((size_t)(b * Hn + h) * NTOK + n) * DHn + d) = v;
        }
    }
}

// ---------------------------------------------------------------------------
// Attention helpers: one block = 32 queries of one head (256 threads).
// Scores held in smem S[32][S_STRIDE]; softmax with 8 threads per row;
// normalization folded into the final output write.
// ---------------------------------------------------------------------------

// Text attention: causal over T=256 text tokens. grid (8 qtiles, 256 bh).
__global__ __launch_bounds__(256) void text_attn_kernel()
{
    extern __shared__ float sm[];
    float* Qs = sm + SM_QS;
    float* KV = sm + SM_KV;
    float* S  = sm + SM_S;

    const int bh = blockIdx.y;
    const int q0 = blockIdx.x * 32;
    const int tid = threadIdx.x;
    const float* qbase = g_q + (size_t)bh * HD;
    const float* kbase = g_k + (size_t)bh * HD;
    const float* vbase = g_v + (size_t)bh * HD;

    // Load Q tile: tokens q0..q0+31
#pragma unroll
    for (int r = 0; r < 2; r++) {
        int idx = tid + 256 * r;
        int row = idx >> 4;
        int c4 = (idx & 15) * 4;
        *(float4*)&Qs[row * QS_STRIDE + c4] =
            *(const float4*)(qbase + (size_t)(q0 + row) * DHn + c4);
    }

    const int nkeys = q0 + 32;
    const int ntiles = (nkeys + 63) >> 6;
    const int qq = tid >> 3;
    const int l8 = tid & 7;
    const int qglob = q0 + qq;

    // ---- scores ----
    for (int kt = 0; kt < ntiles; kt++) {
        const int j0 = kt * 64;
        const int cnt = min(64, nkeys - j0);
        __syncthreads();
#pragma unroll
        for (int r = 0; r < 4; r++) {
            int idx = tid + 256 * r;
            int row = idx >> 4;
            int c4 = (idx & 15) * 4;
            if (row < cnt)
                *(float4*)&KV[row * QS_STRIDE + c4] =
                    *(const float4*)(kbase + (size_t)(j0 + row) * DHn + c4);
        }
        __syncthreads();
        float s[8] = {0.f, 0.f, 0.f, 0.f, 0.f, 0.f, 0.f, 0.f};
#pragma unroll 16
        for (int d = 0; d < 64; d++) {
            float qv = Qs[qq * QS_STRIDE + d];
#pragma unroll
            for (int jj = 0; jj < 8; jj++)
                s[jj] += qv * KV[(l8 + jj * 8) * QS_STRIDE + d];
        }
#pragma unroll
        for (int jj = 0; jj < 8; jj++) {
            int key = j0 + l8 + jj * 8;
            if (key < nkeys)
                S[qq * S_STRIDE + key] = (key <= qglob) ? s[jj] : -FLT_MAX;
        }
    }
    __syncthreads();

    // ---- softmax (unnormalized exp; 8 lanes per row) ----
    float mx = -FLT_MAX;
    for (int j = l8; j < nkeys; j += 8) mx = fmaxf(mx, S[qq * S_STRIDE + j]);
#pragma unroll
    for (int o = 4; o; o >>= 1) mx = fmaxf(mx, __shfl_xor_sync(0xffffffffu, mx, o, 8));
    float sum = 0.f;
    for (int j = l8; j < nkeys; j += 8) {
        float e = __expf(S[qq * S_STRIDE + j] - mx);
        S[qq * S_STRIDE + j] = e;
        sum += e;
    }
#pragma unroll
    for (int o = 4; o; o >>= 1) sum += __shfl_xor_sync(0xffffffffu, sum, o, 8);
    const float inv = 1.0f / sum;

    // ---- AV ----
    float acc[8] = {0.f, 0.f, 0.f, 0.f, 0.f, 0.f, 0.f, 0.f};
    for (int kt = 0; kt < ntiles; kt++) {
        const int j0 = kt * 64;
        const int cnt = min(64, nkeys - j0);
        __syncthreads();
#pragma unroll
        for (int r = 0; r < 4; r++) {
            int idx = tid + 256 * r;
            int row = idx >> 4;
            int c4 = (idx & 15) * 4;
            if (row < cnt)
                *(float4*)&KV[row * QS_STRIDE + c4] =
                    *(const float4*)(vbase + (size_t)(j0 + row) * DHn + c4);
        }
        __syncthreads();
        for (int j = 0; j < cnt; j++) {
            float sv = S[qq * S_STRIDE + j0 + j];
#pragma unroll
            for (int dd = 0; dd < 8; dd++)
                acc[dd] += sv * KV[j * QS_STRIDE + l8 + dd * 8];
        }
    }
    float* obase = g_o + (size_t)bh * HD + (size_t)(q0 + qq) * DHn;
#pragma unroll
    for (int dd = 0; dd < 8; dd++) obase[l8 + dd * 8] = acc[dd] * inv;
}

// Image attention: queries = row xr of the 32x32 image; keys = 256 text
// (unmasked) + 32 same-row image tokens (causal). grid (32 rows, 256 bh).
__global__ __launch_bounds__(256) void img_attn_kernel()
{
    extern __shared__ float sm[];
    float* Qs = sm + SM_QS;
    float* KV = sm + SM_KV;
    float* S  = sm + SM_S;

    const int bh = blockIdx.y;
    const int xr = blockIdx.x;
    const int qtok0 = TXT + xr * 32;
    const int tid = threadIdx.x;
    const float* qbase = g_q + (size_t)bh * HD;
    const float* kbase = g_k + (size_t)bh * HD;
    const float* vbase = g_v + (size_t)bh * HD;

#pragma unroll
    for (int r = 0; r < 2; r++) {
        int idx = tid + 256 * r;
        int row = idx >> 4;
        int c4 = (idx & 15) * 4;
        *(float4*)&Qs[row * QS_STRIDE + c4] =
            *(const float4*)(qbase + (size_t)(qtok0 + row) * DHn + c4);
    }

    const int qq = tid >> 3;
    const int l8 = tid & 7;
    const int ncols = TXT + 32;  // 288

    // ---- scores: 4 text tiles of 64 + 1 image tile of 32 ----
    for (int kt = 0; kt < 5; kt++) {
        const bool imgTile = (kt == 4);
        const int cnt = imgTile ? 32 : 64;
        const int ktok0 = imgTile ? qtok0 : kt * 64;
        __syncthreads();
#pragma unroll
        for (int r = 0; r < 4; r++) {
            int idx = tid + 256 * r;
            int row = idx >> 4;
            int c4 = (idx & 15) * 4;
            if (row < cnt)
                *(float4*)&KV[row * QS_STRIDE + c4] =
                    *(const float4*)(kbase + (size_t)(ktok0 + row) * DHn + c4);
        }
        __syncthreads();
        float s[8] = {0.f, 0.f, 0.f, 0.f, 0.f, 0.f, 0.f, 0.f};
#pragma unroll 16
        for (int d = 0; d < 64; d++) {
            float qv = Qs[qq * QS_STRIDE + d];
#pragma unroll
            for (int jj = 0; jj < 8; jj++)
                s[jj] += qv * KV[(l8 + jj * 8) * QS_STRIDE + d];
        }
        if (!imgTile) {
#pragma unroll
            for (int jj = 0; jj < 8; jj++)
                S[qq * S_STRIDE + kt * 64 + l8 + jj * 8] = s[jj];
        } else {
#pragma unroll
            for (int jj = 0; jj < 4; jj++) {
                int j = l8 + jj * 8;   // 0..31
                S[qq * S_STRIDE + TXT + j] = (j <= qq) ? s[jj] : -FLT_MAX;
            }
        }
    }
    __syncthreads();

    // ---- softmax over 288 ----
    float mx = -FLT_MAX;
    for (int j = l8; j < ncols; j += 8) mx = fmaxf(mx, S[qq * S_STRIDE + j]);
#pragma unroll
    for (int o = 4; o; o >>= 1) mx = fmaxf(mx, __shfl_xor_sync(0xffffffffu, mx, o, 8));
    float sum = 0.f;
    for (int j = l8; j < ncols; j += 8) {
        float e = __expf(S[qq * S_STRIDE + j] - mx);
        S[qq * S_STRIDE + j] = e;
        sum += e;
    }
#pragma unroll
    for (int o = 4; o; o >>= 1) sum += __shfl_xor_sync(0xffffffffu, sum, o, 8);
    const float inv = 1.0f / sum;

    // ---- AV ----
    float acc[8] = {0.f, 0.f, 0.f, 0.f, 0.f, 0.f, 0.f, 0.f};
    for (int kt = 0; kt < 5; kt++) {
        const bool imgTile = (kt == 4);
        const int cnt = imgTile ? 32 : 64;
        const int vtok0 = imgTile ? qtok0 : kt * 64;
        const int scol0 = imgTile ? TXT : kt * 64;
        __syncthreads();
#pragma unroll
        for (int r = 0; r < 4; r++) {
            int idx = tid + 256 * r;
            int row = idx >> 4;
            int c4 = (idx & 15) * 4;
            if (row < cnt)
                *(float4*)&KV[row * QS_STRIDE + c4] =
                    *(const float4*)(vbase + (size_t)(vtok0 + row) * DHn + c4);
        }
        __syncthreads();
        for (int j = 0; j < cnt; j++) {
            float sv = S[qq * S_STRIDE + scol0 + j];
#pragma unroll
            for (int dd = 0; dd < 8; dd++)
                acc[dd] += sv * KV[j * QS_STRIDE + l8 + dd * 8];
        }
    }
    float* obase = g_o + (size_t)bh * HD + (size_t)(qtok0 + qq) * DHn;
#pragma unroll
    for (int dd = 0; dd < 8; dd++) obase[l8 + dd * 8] = acc[dd] * inv;
}

// ---------------------------------------------------------------------------
// Kernel 4: output projection.
// out[b,n,o] = sum_k attn(b,n,k) * w_out[o,k] + b_out[o]; k = h*64+d gathered
// from g_o's (b*H+h, n, d) layout. M=20464, N=1024, K=1024.
// ---------------------------------------------------------------------------
__global__ __launch_bounds__(256) void out_gemm_kernel(
    const float* __restrict__ W, const float* __restrict__ bias,
    float* __restrict__ out)
{
    __shared__ __align__(16) float As[8][128];
    __shared__ __align__(16) float Bs[8][128];

    const int m0  = blockIdx.y * 128;
    const int n0  = blockIdx.x * 128;
    const int tid = threadIdx.x;
    const int tx  = tid & 15;
    const int ty  = tid >> 4;
    const int lrow = tid >> 1;
    const int lcol = (tid & 1) * 4;

    const int am = m0 + lrow;
    const bool avalid = (am < MOUT);
    const int ab = avalid ? (am / NREAL) : 0;
    const int an = avalid ? (am - ab * NREAL) : 0;
    const float* abase = g_o + (size_t)ab * (Hn * HD) + (size_t)an * DHn;
    const float* bptr = W + (size_t)(n0 + lrow) * DIMn;

    float acc[8][8];
#pragma unroll
    for (int i = 0; i < 8; i++)
#pragma unroll
        for (int j = 0; j < 8; j++) acc[i][j] = 0.f;

    // k -> offset (k/64)*HD + (k%64); BK=8 tiles never straddle a 64-chunk.
    {
        const int k = lcol;
        float4 af = avalid ? *(const float4*)(abase + (size_t)(k >> 6) * HD + (k & 63))
                           : make_float4(0.f, 0.f, 0.f, 0.f);
        float4 bf = *(const float4*)(bptr + k);
        for (int k0 = 0; k0 < DIMn; k0 += 8) {
            __syncthreads();
            As[lcol + 0][lrow] = af.x; As[lcol + 1][lrow] = af.y;
            As[lcol + 2][lrow] = af.z; As[lcol + 3][lrow] = af.w;
            Bs[lcol + 0][lrow] = bf.x; Bs[lcol + 1][lrow] = bf.y;
            Bs[lcol + 2][lrow] = bf.z; Bs[lcol + 3][lrow] = bf.w;
            __syncthreads();
            if (k0 + 8 < DIMn) {
                const int kn = k0 + 8 + lcol;
                af = avalid ? *(const float4*)(abase + (size_t)(kn >> 6) * HD + (kn & 63))
                            : make_float4(0.f, 0.f, 0.f, 0.f);
                bf = *(const float4*)(bptr + k0 + 8 + lcol);
            }
#pragma unroll
            for (int kk = 0; kk < 8; kk++) {
                float4 a0 = *(const float4*)&As[kk][ty * 4];
                float4 a1 = *(const float4*)&As[kk][64 + ty * 4];
                float4 b0 = *(const float4*)&Bs[kk][tx * 4];
                float4 b1 = *(const float4*)&Bs[kk][64 + tx * 4];
                float av[8] = {a0.x, a0.y, a0.z, a0.w, a1.x, a1.y, a1.z, a1.w};
                float bv[8] = {b0.x, b0.y, b0.z, b0.w, b1.x, b1.y, b1.z, b1.w};
#pragma unroll
                for (int i = 0; i < 8; i++)
#pragma unroll
                    for (int j = 0; j < 8; j++) acc[i][j] += av[i] * bv[j];
            }
        }
    }

#pragma unroll
    for (int i = 0; i < 8; i++) {
        const int mrow = m0 + ((i < 4) ? (ty * 4 + i) : (64 + ty * 4 + i - 4));
        if (mrow >= MOUT) continue;
#pragma unroll
        for (int jg = 0; jg < 2; jg++) {
            const int col = n0 + ((jg == 0) ? (tx * 4) : (64 + tx * 4));
            float4 bb = *(const float4*)(bias + col);
            float4 v;
            v.x = acc[i][jg * 4 + 0] + bb.x;
            v.y = acc[i][jg * 4 + 1] + bb.y;
            v.z = acc[i][jg * 4 + 2] + bb.z;
            v.w = acc[i][jg * 4 + 3] + bb.w;
            *(float4*)(out + (size_t)mrow * DIMn + col) = v;
        }
    }
}

// ---------------------------------------------------------------------------
// Launch
// ---------------------------------------------------------------------------
extern "C" void kernel_launch(void* const* d_in, const int* in_sizes, int n_in,
                              void* d_out, int out_size)
{
    (void)in_sizes; (void)n_in; (void)out_size;
    const float* x     = (const float*)d_in[0];
    const float* w_qkv = (const float*)d_in[1];
    const float* w_out = (const float*)d_in[2];
    const float* b_out = (const float*)d_in[3];
    float* out = (float*)d_out;

    cudaFuncSetAttribute(text_attn_kernel,
                         cudaFuncAttributeMaxDynamicSharedMemorySize, SMEM_ATTN_BYTES);
    cudaFuncSetAttribute(img_attn_kernel,
                         cudaFuncAttributeMaxDynamicSharedMemorySize, SMEM_ATTN_BYTES);

    // 1) QKV projection into head-layout scratch (q pre-scaled)
    qkv_gemm_kernel<<<dim3(24, 160), 256>>>(x, w_qkv);
    // 2) text causal attention (tokens 0..255)
    text_attn_kernel<<<dim3(8, 256), 256, SMEM_ATTN_BYTES>>>();
    // 3) axial image attention (tokens 256..1279)
    img_attn_kernel<<<dim3(32, 256), 256, SMEM_ATTN_BYTES>>>();
    // 4) output projection + bias, writes only the 1279 real rows
    out_gemm_kernel<<<dim3(8, 160), 256>>>(w_out, b_out, out);
}

// round 2
// speedup vs baseline: 1.6406x; 1.6406x over previous
#include <cuda_runtime.h>
#include <float.h>

// ---------------------------------------------------------------------------
// Problem constants
// ---------------------------------------------------------------------------
#define Bn     16
#define Hn     16
#define DHn    64
#define NTOK   1280          // padded sequence (SEQ_LEN + 1)
#define NREAL  1279          // real tokens
#define DIMn   1024
#define TXT    256           // text length
#define BH     256           // Bn * Hn
#define HD     (NTOK * DHn)  // 81920 floats per (b,h) plane
#define MQKV   (Bn * NTOK)   // 20480
#define MOUT   (Bn * NREAL)  // 20464
#define QSCALE 0.125f        // DH^-0.5

// Attention smem layout (floats): Qs[32][68], KV[64][68], S[32][292]
#define QS_STRIDE 68
#define S_STRIDE  292
#define SM_QS 0
#define SM_KV (32 * QS_STRIDE)
#define SM_S  (32 * QS_STRIDE + 64 * QS_STRIDE)
#define SMEM_ATTN_BYTES ((32 * QS_STRIDE + 64 * QS_STRIDE + 32 * S_STRIDE) * 4)

// GEMM smem stride (floats). bank = 8*(lane%4) + lane/4 -> conflict-free frags.
#define KS 136

// ---------------------------------------------------------------------------
// Scratch (device globals: allocation-free)
// ---------------------------------------------------------------------------
__device__ float g_q[BH * HD];
__device__ float g_k[BH * HD];
__device__ float g_v[BH * HD];
__device__ float g_o[BH * HD];

// ---------------------------------------------------------------------------
// TF32 helpers
// ---------------------------------------------------------------------------
__device__ __forceinline__ float f2tf32(float x) {
    unsigned t;
    asm("cvt.rna.tf32.f32 %0, %1;" : "=r"(t) : "f"(x));
    return __uint_as_float(t);
}

__device__ __forceinline__ void mma_tf32(float c[4], const unsigned a[4],
                                         const unsigned b[2]) {
    asm volatile(
        "mma.sync.aligned.m16n8k8.row.col.f32.tf32.tf32.f32 "
        "{%0,%1,%2,%3}, {%4,%5,%6,%7}, {%8,%9}, {%0,%1,%2,%3};\n"
        : "+f"(c[0]), "+f"(c[1]), "+f"(c[2]), "+f"(c[3])
        : "r"(a[0]), "r"(a[1]), "r"(a[2]), "r"(a[3]), "r"(b[0]), "r"(b[1]));
}

// ---------------------------------------------------------------------------
// Kernel 1: fused QKV projection (TF32 tensor cores).
// C[m, j] = sum_k xp[m,k] * w_qkv[j,k].  Block tile 128x128x16, 8 warps,
// warp tile 32x64 (2x8 m16n8k8 tiles). Epilogue scatters to head layout.
// ---------------------------------------------------------------------------
__global__ __launch_bounds__(256) void qkv_gemm_kernel(
    const float* __restrict__ X, const float* __restrict__ W)
{
    __shared__ __align__(16) float As[16 * KS];
    __shared__ __align__(16) float Bs[16 * KS];

    const int m0  = blockIdx.y * 128;
    const int n0  = blockIdx.x * 128;
    const int tid = threadIdx.x;
    const int lane = tid & 31;
    const int warp = tid >> 5;
    const int warpM = warp >> 1;        // 0..3
    const int warpN = warp & 1;         // 0..1
    const int grp = lane >> 2;          // 0..7
    const int qd  = lane & 3;           // 0..3

    // loader mapping: row = tid>>1, two float4 at cols (tid&1)*8 + {0,4}
    const int lrow = tid >> 1;
    const int lk   = (tid & 1) * 8;

    const int am = m0 + lrow;
    const int ab = am / NTOK;
    const int an = am - ab * NTOK;
    const bool avalid = (an < NREAL);
    const float* aptr = X + ((size_t)ab * NREAL + an) * DIMn;
    const float* bptr = W + (size_t)(n0 + lrow) * DIMn;

    float c[2][8][4];
#pragma unroll
    for (int tm = 0; tm < 2; tm++)
#pragma unroll
        for (int tn = 0; tn < 8; tn++)
#pragma unroll
            for (int i = 0; i < 4; i++) c[tm][tn][i] = 0.f;

    float4 af0, af1, bf0, bf1;
    af0 = avalid ? *(const float4*)(aptr + lk)     : make_float4(0,0,0,0);
    af1 = avalid ? *(const float4*)(aptr + lk + 4) : make_float4(0,0,0,0);
    bf0 = *(const float4*)(bptr + lk);
    bf1 = *(const float4*)(bptr + lk + 4);

    for (int k0 = 0; k0 < DIMn; k0 += 16) {
        // store (converted to tf32) into smem [k][m]
        As[(lk + 0) * KS + lrow] = f2tf32(af0.x);
        As[(lk + 1) * KS + lrow] = f2tf32(af0.y);
        As[(lk + 2) * KS + lrow] = f2tf32(af0.z);
        As[(lk + 3) * KS + lrow] = f2tf32(af0.w);
        As[(lk + 4) * KS + lrow] = f2tf32(af1.x);
        As[(lk + 5) * KS + lrow] = f2tf32(af1.y);
        As[(lk + 6) * KS + lrow] = f2tf32(af1.z);
        As[(lk + 7) * KS + lrow] = f2tf32(af1.w);
        Bs[(lk + 0) * KS + lrow] = f2tf32(bf0.x);
        Bs[(lk + 1) * KS + lrow] = f2tf32(bf0.y);
        Bs[(lk + 2) * KS + lrow] = f2tf32(bf0.z);
        Bs[(lk + 3) * KS + lrow] = f2tf32(bf0.w);
        Bs[(lk + 4) * KS + lrow] = f2tf32(bf1.x);
        Bs[(lk + 5) * KS + lrow] = f2tf32(bf1.y);
        Bs[(lk + 6) * KS + lrow] = f2tf32(bf1.z);
        Bs[(lk + 7) * KS + lrow] = f2tf32(bf1.w);
        __syncthreads();

        if (k0 + 16 < DIMn) {
            const int kn = k0 + 16 + lk;
            af0 = avalid ? *(const float4*)(aptr + kn)     : make_float4(0,0,0,0);
            af1 = avalid ? *(const float4*)(aptr + kn + 4) : make_float4(0,0,0,0);
            bf0 = *(const float4*)(bptr + kn);
            bf1 = *(const float4*)(bptr + kn + 4);
        }

#pragma unroll
        for (int ks = 0; ks < 2; ks++) {
            const int kk = ks * 8;
            unsigned a[2][4], b[8][2];
#pragma unroll
            for (int tm = 0; tm < 2; tm++) {
                const int r0 = warpM * 32 + tm * 16 + grp;
                a[tm][0] = __float_as_uint(As[(kk + qd) * KS + r0]);
                a[tm][1] = __float_as_uint(As[(kk + qd) * KS + r0 + 8]);
                a[tm][2] = __float_as_uint(As[(kk + qd + 4) * KS + r0]);
                a[tm][3] = __float_as_uint(As[(kk + qd + 4) * KS + r0 + 8]);
            }
#pragma unroll
            for (int tn = 0; tn < 8; tn++) {
                const int cc = warpN * 64 + tn * 8 + grp;
                b[tn][0] = __float_as_uint(Bs[(kk + qd) * KS + cc]);
                b[tn][1] = __float_as_uint(Bs[(kk + qd + 4) * KS + cc]);
            }
#pragma unroll
            for (int tm = 0; tm < 2; tm++)
#pragma unroll
                for (int tn = 0; tn < 8; tn++)
                    mma_tf32(c[tm][tn], a[tm], b[tn]);
        }
        __syncthreads();
    }

    // Epilogue: scatter into g_q / g_k / g_v with head layout, scale Q.
#pragma unroll
    for (int tm = 0; tm < 2; tm++) {
#pragma unroll
        for (int half = 0; half < 2; half++) {
            const int mrow = m0 + warpM * 32 + tm * 16 + grp + half * 8;
            const int b_ = mrow / NTOK;
            const int n_ = mrow - b_ * NTOK;
#pragma unroll
            for (int tn = 0; tn < 8; tn++) {
                const int col = n0 + warpN * 64 + tn * 8 + qd * 2;
                const int which = col >> 10;       // 0=q 1=k 2=v
                const int cc = col & 1023;
                const int h = cc >> 6;
                const int d = cc & 63;
                float* dst = (which == 0) ? g_q : ((which == 1) ? g_k : g_v);
                const float sc = (which == 0) ? QSCALE : 1.0f;
                float2 v;
                v.x = c[tm][tn][half * 2 + 0] * sc;
                v.y = c[tm][tn][half * 2 + 1] * sc;
                *(float2*)(dst + ((size_t)(b_ * Hn + h) * NTOK + n_) * DHn + d) = v;
            }
        }
    }
}

// ---------------------------------------------------------------------------
// Attention: one block = 32 queries of one head (256 threads). fp32.
// ---------------------------------------------------------------------------
__global__ __launch_bounds__(256) void text_attn_kernel()
{
    extern __shared__ float sm[];
    float* Qs = sm + SM_QS;
    float* KV = sm + SM_KV;
    float* S  = sm + SM_S;

    const int bh = blockIdx.y;
    const int q0 = blockIdx.x * 32;
    const int tid = threadIdx.x;
    const float* qbase = g_q + (size_t)bh * HD;
    const float* kbase = g_k + (size_t)bh * HD;
    const float* vbase = g_v + (size_t)bh * HD;

#pragma unroll
    for (int r = 0; r < 2; r++) {
        int idx = tid + 256 * r;
        int row = idx >> 4;
        int c4 = (idx & 15) * 4;
        *(float4*)&Qs[row * QS_STRIDE + c4] =
            *(const float4*)(qbase + (size_t)(q0 + row) * DHn + c4);
    }

    const int nkeys = q0 + 32;
    const int ntiles = (nkeys + 63) >> 6;
    const int qq = tid >> 3;
    const int l8 = tid & 7;
    const int qglob = q0 + qq;

    for (int kt = 0; kt < ntiles; kt++) {
        const int j0 = kt * 64;
        const int cnt = min(64, nkeys - j0);
        __syncthreads();
#pragma unroll
        for (int r = 0; r < 4; r++) {
            int idx = tid + 256 * r;
            int row = idx >> 4;
            int c4 = (idx & 15) * 4;
            if (row < cnt)
                *(float4*)&KV[row * QS_STRIDE + c4] =
                    *(const float4*)(kbase + (size_t)(j0 + row) * DHn + c4);
        }
        __syncthreads();
        float s[8] = {0,0,0,0,0,0,0,0};
#pragma unroll 16
        for (int d = 0; d < 64; d++) {
            float qv = Qs[qq * QS_STRIDE + d];
#pragma unroll
            for (int jj = 0; jj < 8; jj++)
                s[jj] += qv * KV[(l8 + jj * 8) * QS_STRIDE + d];
        }
#pragma unroll
        for (int jj = 0; jj < 8; jj++) {
            int key = j0 + l8 + jj * 8;
            if (key < nkeys)
                S[qq * S_STRIDE + key] = (key <= qglob) ? s[jj] : -FLT_MAX;
        }
    }
    __syncthreads();

    float mx = -FLT_MAX;
    for (int j = l8; j < nkeys; j += 8) mx = fmaxf(mx, S[qq * S_STRIDE + j]);
#pragma unroll
    for (int o = 4; o; o >>= 1) mx = fmaxf(mx, __shfl_xor_sync(0xffffffffu, mx, o, 8));
    float sum = 0.f;
    for (int j = l8; j < nkeys; j += 8) {
        float e = __expf(S[qq * S_STRIDE + j] - mx);
        S[qq * S_STRIDE + j] = e;
        sum += e;
    }
#pragma unroll
    for (int o = 4; o; o >>= 1) sum += __shfl_xor_sync(0xffffffffu, sum, o, 8);
    const float inv = 1.0f / sum;

    float acc[8] = {0,0,0,0,0,0,0,0};
    for (int kt = 0; kt < ntiles; kt++) {
        const int j0 = kt * 64;
        const int cnt = min(64, nkeys - j0);
        __syncthreads();
#pragma unroll
        for (int r = 0; r < 4; r++) {
            int idx = tid + 256 * r;
            int row = idx >> 4;
            int c4 = (idx & 15) * 4;
            if (row < cnt)
                *(float4*)&KV[row * QS_STRIDE + c4] =
                    *(const float4*)(vbase + (size_t)(j0 + row) * DHn + c4);
        }
        __syncthreads();
        for (int j = 0; j < cnt; j++) {
            float sv = S[qq * S_STRIDE + j0 + j];
#pragma unroll
            for (int dd = 0; dd < 8; dd++)
                acc[dd] += sv * KV[j * QS_STRIDE + l8 + dd * 8];
        }
    }
    float* obase = g_o + (size_t)bh * HD + (size_t)(q0 + qq) * DHn;
#pragma unroll
    for (int dd = 0; dd < 8; dd++) obase[l8 + dd * 8] = acc[dd] * inv;
}

__global__ __launch_bounds__(256) void img_attn_kernel()
{
    extern __shared__ float sm[];
    float* Qs = sm + SM_QS;
    float* KV = sm + SM_KV;
    float* S  = sm + SM_S;

    const int bh = blockIdx.y;
    const int xr = blockIdx.x;
    const int qtok0 = TXT + xr * 32;
    const int tid = threadIdx.x;
    const float* qbase = g_q + (size_t)bh * HD;
    const float* kbase = g_k + (size_t)bh * HD;
    const float* vbase = g_v + (size_t)bh * HD;

#pragma unroll
    for (int r = 0; r < 2; r++) {
        int idx = tid + 256 * r;
        int row = idx >> 4;
        int c4 = (idx & 15) * 4;
        *(float4*)&Qs[row * QS_STRIDE + c4] =
            *(const float4*)(qbase + (size_t)(qtok0 + row) * DHn + c4);
    }

    const int qq = tid >> 3;
    const int l8 = tid & 7;
    const int ncols = TXT + 32;

    for (int kt = 0; kt < 5; kt++) {
        const bool imgTile = (kt == 4);
        const int cnt = imgTile ? 32 : 64;
        const int ktok0 = imgTile ? qtok0 : kt * 64;
        __syncthreads();
#pragma unroll
        for (int r = 0; r < 4; r++) {
            int idx = tid + 256 * r;
            int row = idx >> 4;
            int c4 = (idx & 15) * 4;
            if (row < cnt)
                *(float4*)&KV[row * QS_STRIDE + c4] =
                    *(const float4*)(kbase + (size_t)(ktok0 + row) * DHn + c4);
        }
        __syncthreads();
        float s[8] = {0,0,0,0,0,0,0,0};
#pragma unroll 16
        for (int d = 0; d < 64; d++) {
            float qv = Qs[qq * QS_STRIDE + d];
#pragma unroll
            for (int jj = 0; jj < 8; jj++)
                s[jj] += qv * KV[(l8 + jj * 8) * QS_STRIDE + d];
        }
        if (!imgTile) {
#pragma unroll
            for (int jj = 0; jj < 8; jj++)
                S[qq * S_STRIDE + kt * 64 + l8 + jj * 8] = s[jj];
        } else {
#pragma unroll
            for (int jj = 0; jj < 4; jj++) {
                int j = l8 + jj * 8;
                S[qq * S_STRIDE + TXT + j] = (j <= qq) ? s[jj] : -FLT_MAX;
            }
        }
    }
    __syncthreads();

    float mx = -FLT_MAX;
    for (int j = l8; j < ncols; j += 8) mx = fmaxf(mx, S[qq * S_STRIDE + j]);
#pragma unroll
    for (int o = 4; o; o >>= 1) mx = fmaxf(mx, __shfl_xor_sync(0xffffffffu, mx, o, 8));
    float sum = 0.f;
    for (int j = l8; j < ncols; j += 8) {
        float e = __expf(S[qq * S_STRIDE + j] - mx);
        S[qq * S_STRIDE + j] = e;
        sum += e;
    }
#pragma unroll
    for (int o = 4; o; o >>= 1) sum += __shfl_xor_sync(0xffffffffu, sum, o, 8);
    const float inv = 1.0f / sum;

    float acc[8] = {0,0,0,0,0,0,0,0};
    for (int kt = 0; kt < 5; kt++) {
        const bool imgTile = (kt == 4);
        const int cnt = imgTile ? 32 : 64;
        const int vtok0 = imgTile ? qtok0 : kt * 64;
        const int scol0 = imgTile ? TXT : kt * 64;
        __syncthreads();
#pragma unroll
        for (int r = 0; r < 4; r++) {
            int idx = tid + 256 * r;
            int row = idx >> 4;
            int c4 = (idx & 15) * 4;
            if (row < cnt)
                *(float4*)&KV[row * QS_STRIDE + c4] =
                    *(const float4*)(vbase + (size_t)(vtok0 + row) * DHn + c4);
        }
        __syncthreads();
        for (int j = 0; j < cnt; j++) {
            float sv = S[qq * S_STRIDE + scol0 + j];
#pragma unroll
            for (int dd = 0; dd < 8; dd++)
                acc[dd] += sv * KV[j * QS_STRIDE + l8 + dd * 8];
        }
    }
    float* obase = g_o + (size_t)bh * HD + (size_t)(qtok0 + qq) * DHn;
#pragma unroll
    for (int dd = 0; dd < 8; dd++) obase[l8 + dd * 8] = acc[dd] * inv;
}

// ---------------------------------------------------------------------------
// Kernel 4: output projection (TF32 tensor cores).
// out[b,n,o] = sum_k attn(b,n,k) * w_out[o,k] + b_out[o]
// ---------------------------------------------------------------------------
__global__ __launch_bounds__(256) void out_gemm_kernel(
    const float* __restrict__ W, const float* __restrict__ bias,
    float* __restrict__ out)
{
    __shared__ __align__(16) float As[16 * KS];
    __shared__ __align__(16) float Bs[16 * KS];

    const int m0  = blockIdx.y * 128;
    const int n0  = blockIdx.x * 128;
    const int tid = threadIdx.x;
    const int lane = tid & 31;
    const int warp = tid >> 5;
    const int warpM = warp >> 1;
    const int warpN = warp & 1;
    const int grp = lane >> 2;
    const int qd  = lane & 3;

    const int lrow = tid >> 1;
    const int lk   = (tid & 1) * 8;

    const int am = m0 + lrow;
    const bool avalid = (am < MOUT);
    const int ab = avalid ? (am / NREAL) : 0;
    const int an = avalid ? (am - ab * NREAL) : 0;
    const float* abase = g_o + (size_t)ab * (Hn * HD) + (size_t)an * DHn;
    const float* bptr = W + (size_t)(n0 + lrow) * DIMn;

    float c[2][8][4];
#pragma unroll
    for (int tm = 0; tm < 2; tm++)
#pragma unroll
        for (int tn = 0; tn < 8; tn++)
#pragma unroll
            for (int i = 0; i < 4; i++) c[tm][tn][i] = 0.f;

    // k -> offset (k/64)*HD + (k%64); BK=16 tiles never straddle a 64-chunk.
    float4 af0, af1, bf0, bf1;
    {
        const int k = lk;
        af0 = avalid ? *(const float4*)(abase + (size_t)(k >> 6) * HD + (k & 63))
                     : make_float4(0,0,0,0);
        af1 = avalid ? *(const float4*)(abase + (size_t)((k+4) >> 6) * HD + ((k+4) & 63))
                     : make_float4(0,0,0,0);
        bf0 = *(const float4*)(bptr + k);
        bf1 = *(const float4*)(bptr + k + 4);
    }

    for (int k0 = 0; k0 < DIMn; k0 += 16) {
        As[(lk + 0) * KS + lrow] = f2tf32(af0.x);
        As[(lk + 1) * KS + lrow] = f2tf32(af0.y);
        As[(lk + 2) * KS + lrow] = f2tf32(af0.z);
        As[(lk + 3) * KS + lrow] = f2tf32(af0.w);
        As[(lk + 4) * KS + lrow] = f2tf32(af1.x);
        As[(lk + 5) * KS + lrow] = f2tf32(af1.y);
        As[(lk + 6) * KS + lrow] = f2tf32(af1.z);
        As[(lk + 7) * KS + lrow] = f2tf32(af1.w);
        Bs[(lk + 0) * KS + lrow] = f2tf32(bf0.x);
        Bs[(lk + 1) * KS + lrow] = f2tf32(bf0.y);
        Bs[(lk + 2) * KS + lrow] = f2tf32(bf0.z);
        Bs[(lk + 3) * KS + lrow] = f2tf32(bf0.w);
        Bs[(lk + 4) * KS + lrow] = f2tf32(bf1.x);
        Bs[(lk + 5) * KS + lrow] = f2tf32(bf1.y);
        Bs[(lk + 6) * KS + lrow] = f2tf32(bf1.z);
        Bs[(lk + 7) * KS + lrow] = f2tf32(bf1.w);
        __syncthreads();

        if (k0 + 16 < DIMn) {
            const int kn = k0 + 16 + lk;
            af0 = avalid ? *(const float4*)(abase + (size_t)(kn >> 6) * HD + (kn & 63))
                         : make_float4(0,0,0,0);
            af1 = avalid ? *(const float4*)(abase + (size_t)((kn+4) >> 6) * HD + ((kn+4) & 63))
                         : make_float4(0,0,0,0);
            bf0 = *(const float4*)(bptr + kn);
            bf1 = *(const float4*)(bptr + kn + 4);
        }

#pragma unroll
        for (int ks = 0; ks < 2; ks++) {
            const int kk = ks * 8;
            unsigned a[2][4], b[8][2];
#pragma unroll
            for (int tm = 0; tm < 2; tm++) {
                const int r0 = warpM * 32 + tm * 16 + grp;
                a[tm][0] = __float_as_uint(As[(kk + qd) * KS + r0]);
                a[tm][1] = __float_as_uint(As[(kk + qd) * KS + r0 + 8]);
                a[tm][2] = __float_as_uint(As[(kk + qd + 4) * KS + r0]);
                a[tm][3] = __float_as_uint(As[(kk + qd + 4) * KS + r0 + 8]);
            }
#pragma unroll
            for (int tn = 0; tn < 8; tn++) {
                const int cc = warpN * 64 + tn * 8 + grp;
                b[tn][0] = __float_as_uint(Bs[(kk + qd) * KS + cc]);
                b[tn][1] = __float_as_uint(Bs[(kk + qd + 4) * KS + cc]);
            }
#pragma unroll
            for (int tm = 0; tm < 2; tm++)
#pragma unroll
                for (int tn = 0; tn < 8; tn++)
                    mma_tf32(c[tm][tn], a[tm], b[tn]);
        }
        __syncthreads();
    }

#pragma unroll
    for (int tm = 0; tm < 2; tm++) {
#pragma unroll
        for (int half = 0; half < 2; half++) {
            const int mrow = m0 + warpM * 32 + tm * 16 + grp + half * 8;
            if (mrow >= MOUT) continue;
#pragma unroll
            for (int tn = 0; tn < 8; tn++) {
                const int col = n0 + warpN * 64 + tn * 8 + qd * 2;
                float2 bb = *(const float2*)(bias + col);
                float2 v;
                v.x = c[tm][tn][half * 2 + 0] + bb.x;
                v.y = c[tm][tn][half * 2 + 1] + bb.y;
                *(float2*)(out + (size_t)mrow * DIMn + col) = v;
            }
        }
    }
}

// ---------------------------------------------------------------------------
// Launch
// ---------------------------------------------------------------------------
extern "C" void kernel_launch(void* const* d_in, const int* in_sizes, int n_in,
                              void* d_out, int out_size)
{
    (void)in_sizes; (void)n_in; (void)out_size;
    const float* x     = (const float*)d_in[0];
    const float* w_qkv = (const float*)d_in[1];
    const float* w_out = (const float*)d_in[2];
    const float* b_out = (const float*)d_in[3];
    float* out = (float*)d_out;

    cudaFuncSetAttribute(text_attn_kernel,
                         cudaFuncAttributeMaxDynamicSharedMemorySize, SMEM_ATTN_BYTES);
    cudaFuncSetAttribute(img_attn_kernel,
                         cudaFuncAttributeMaxDynamicSharedMemorySize, SMEM_ATTN_BYTES);

    // 1) QKV projection into head-layout scratch (q pre-scaled)
    qkv_gemm_kernel<<<dim3(24, 160), 256>>>(x, w_qkv);
    // 2) text causal attention (tokens 0..255)
    text_attn_kernel<<<dim3(8, 256), 256, SMEM_ATTN_BYTES>>>();
    // 3) axial image attention (tokens 256..1279)
    img_attn_kernel<<<dim3(32, 256), 256, SMEM_ATTN_BYTES>>>();
    // 4) output projection + bias, writes only the 1279 real rows
    out_gemm_kernel<<<dim3(8, 160), 256>>>(w_out, b_out, out);
}

// round 3
// speedup vs baseline: 2.4755x; 1.5089x over previous
#include <cuda_runtime.h>
#include <cuda_fp16.h>
#include <float.h>

// ---------------------------------------------------------------------------
// Problem constants
// ---------------------------------------------------------------------------
#define Bn     16
#define Hn     16
#define DHn    64
#define NTOK   1280          // padded sequence (SEQ_LEN + 1)
#define NREAL  1279          // real tokens
#define DIMn   1024
#define TXT    256           // text length
#define BH     256           // Bn * Hn
#define HD     (NTOK * DHn)  // 81920 floats per (b,h) plane
#define MQKV   (Bn * NTOK)   // 20480
#define MOUT   (Bn * NREAL)  // 20464
#define QSCALE 0.125f        // DH^-0.5

// Attention smem layout (floats): Qs[32][68], KV[64][68], S[32][292]
#define QS_STRIDE 68
#define S_STRIDE  292
#define SM_QS 0
#define SM_KV (32 * QS_STRIDE)
#define SM_S  (32 * QS_STRIDE + 64 * QS_STRIDE)
#define SMEM_ATTN_BYTES ((32 * QS_STRIDE + 64 * QS_STRIDE + 32 * S_STRIDE) * 4)

// ---------------------------------------------------------------------------
// Scratch (device globals: allocation-free)
// ---------------------------------------------------------------------------
__device__ float  g_q[BH * HD];
__device__ float  g_k[BH * HD];
__device__ float  g_v[BH * HD];
__device__ float  g_o[BH * HD];
__device__ __half g_xh[(size_t)MQKV * DIMn];     // padded x in fp16
__device__ __half g_wqkvh[3 * DIMn * DIMn];      // w_qkv fp16
__device__ __half g_wouth[DIMn * DIMn];          // w_out fp16
__device__ __half g_oh[(size_t)MOUT * DIMn];     // attn out, de-interleaved fp16

// ---------------------------------------------------------------------------
// fp16 MMA helpers
// ---------------------------------------------------------------------------
__device__ __forceinline__ void mma_f16(float c[4], const unsigned a[4],
                                        const unsigned b[2]) {
    asm volatile(
        "mma.sync.aligned.m16n8k16.row.col.f32.f16.f16.f32 "
        "{%0,%1,%2,%3}, {%4,%5,%6,%7}, {%8,%9}, {%0,%1,%2,%3};\n"
        : "+f"(c[0]), "+f"(c[1]), "+f"(c[2]), "+f"(c[3])
        : "r"(a[0]), "r"(a[1]), "r"(a[2]), "r"(a[3]), "r"(b[0]), "r"(b[1]));
}

__device__ __forceinline__ void ldsm4(unsigned& r0, unsigned& r1,
                                      unsigned& r2, unsigned& r3, unsigned addr) {
    asm volatile("ldmatrix.sync.aligned.m8n8.x4.shared.b16 {%0,%1,%2,%3}, [%4];\n"
                 : "=r"(r0), "=r"(r1), "=r"(r2), "=r"(r3) : "r"(addr));
}

// Swizzled smem offset (bytes) for tile row 'row' (0..127), 16B-chunk 'c' (0..3)
__device__ __forceinline__ unsigned swz(int row, int c) {
    return (unsigned)(row * 64 + ((c ^ ((row >> 1) & 3)) << 4));
}

__device__ __forceinline__ void cp16(unsigned dst, const void* src, bool v) {
    int sz = v ? 16 : 0;
    asm volatile("cp.async.cg.shared.global [%0], [%1], 16, %2;\n"
                 :: "r"(dst), "l"(src), "r"(sz) : "memory");
}
__device__ __forceinline__ void cp_commit() {
    asm volatile("cp.async.commit_group;\n" ::: "memory");
}
__device__ __forceinline__ void cp_wait1() {
    asm volatile("cp.async.wait_group 1;\n" ::: "memory");
}

// ---------------------------------------------------------------------------
// fp16 HGEMM, C[m,n] = sum_k A[m,k]*B[n,k]. 128x128x32 tile, 3-stage cp.async
// pipeline, ldmatrix.x4 fragments, fp32 accumulate.
// EPI=0: scatter to g_q/g_k/g_v head layout (Q scaled). EPI=1: out + bias.
// ---------------------------------------------------------------------------
template <int EPI>
__global__ __launch_bounds__(256, 2) void hgemm_kernel(
    const __half* __restrict__ A, const __half* __restrict__ B,
    const float* __restrict__ bias, float* __restrict__ out, int Mv)
{
    __shared__ __align__(16) __half smem[3 * 2 * 128 * 32];  // 49152 B
    const unsigned smbase = (unsigned)__cvta_generic_to_shared(smem);

    const int tid = threadIdx.x;
    const int m0 = blockIdx.y * 128;
    const int n0 = blockIdx.x * 128;

    // loader mapping: row = tid>>1, chunks (tid&1)*2 + {0,1}
    const int lr = tid >> 1;
    const int lc = (tid & 1) * 2;
    const __half* gA = A + (size_t)(m0 + lr) * DIMn + lc * 8;
    const __half* gB = B + (size_t)(n0 + lr) * DIMn + lc * 8;
    const bool av = (m0 + lr) < Mv;
    const unsigned dA0 = swz(lr, lc), dA1 = swz(lr, lc + 1);

    auto load_stage = [&](int s, int k0) {
        unsigned sb = smbase + s * 16384;
        const __half* pa = gA + k0;
        const __half* pb = gB + k0;
        cp16(sb + dA0, pa, av);
        cp16(sb + dA1, pa + 8, av);
        cp16(sb + 8192 + dA0, pb, true);
        cp16(sb + 8192 + dA1, pb + 8, true);
    };

    const int lane = tid & 31, warp = tid >> 5;
    const int wM = warp >> 1, wN = warp & 1;   // warps 4x2, warp tile 32x64
    const int aRow = wM * 32 + (lane & 15);
    const int aCb  = lane >> 4;
    const int bRow = wN * 64 + (lane & 7) + ((lane >> 4) & 1) * 8;
    const int bCb  = (lane >> 3) & 1;

    float c[2][8][4];
#pragma unroll
    for (int tm = 0; tm < 2; tm++)
#pragma unroll
        for (int tn = 0; tn < 8; tn++)
#pragma unroll
            for (int i = 0; i < 4; i++) c[tm][tn][i] = 0.f;

    load_stage(0, 0);  cp_commit();
    load_stage(1, 32); cp_commit();

    for (int it = 0; it < 32; it++) {
        cp_wait1();
        __syncthreads();
        if (it + 2 < 32) load_stage((it + 2) % 3, (it + 2) * 32);
        cp_commit();

        const unsigned sb = smbase + (it % 3) * 16384;
#pragma unroll
        for (int k16 = 0; k16 < 2; k16++) {
            unsigned a[2][4], b[4][4];
#pragma unroll
            for (int tm = 0; tm < 2; tm++)
                ldsm4(a[tm][0], a[tm][1], a[tm][2], a[tm][3],
                      sb + swz(aRow + tm * 16, aCb + 2 * k16));
#pragma unroll
            for (int p = 0; p < 4; p++)
                ldsm4(b[p][0], b[p][1], b[p][2], b[p][3],
                      sb + 8192 + swz(bRow + p * 16, bCb + 2 * k16));
#pragma unroll
            for (int tm = 0; tm < 2; tm++)
#pragma unroll
                for (int tn = 0; tn < 8; tn++)
                    mma_f16(c[tm][tn], a[tm], &b[tn >> 1][(tn & 1) * 2]);
        }
    }

    const int grp = lane >> 2, qd = lane & 3;
#pragma unroll
    for (int tm = 0; tm < 2; tm++) {
#pragma unroll
        for (int hf = 0; hf < 2; hf++) {
            const int mrow = m0 + wM * 32 + tm * 16 + grp + hf * 8;
            if (EPI == 0) {
                const int b_ = mrow / NTOK;
                const int n_ = mrow - b_ * NTOK;
#pragma unroll
                for (int tn = 0; tn < 8; tn++) {
                    const int col = n0 + wN * 64 + tn * 8 + qd * 2;
                    const int which = col >> 10;
                    const int cc = col & 1023;
                    const int h = cc >> 6;
                    const int d = cc & 63;
                    float* dst = (which == 0) ? g_q : ((which == 1) ? g_k : g_v);
                    const float sc = (which == 0) ? QSCALE : 1.0f;
                    float2 v;
                    v.x = c[tm][tn][hf * 2 + 0] * sc;
                    v.y = c[tm][tn][hf * 2 + 1] * sc;
                    *(float2*)(dst + ((size_t)(b_ * Hn + h) * NTOK + n_) * DHn + d) = v;
                }
            } else {
                if (mrow < Mv) {
#pragma unroll
                    for (int tn = 0; tn < 8; tn++) {
                        const int col = n0 + wN * 64 + tn * 8 + qd * 2;
                        float2 bb = *(const float2*)(bias + col);
                        float2 v;
                        v.x = c[tm][tn][hf * 2 + 0] + bb.x;
                        v.y = c[tm][tn][hf * 2 + 1] + bb.y;
                        *(float2*)(out + (size_t)mrow * DIMn + col) = v;
                    }
                }
            }
        }
    }
}

// ---------------------------------------------------------------------------
// fp32 -> fp16 conversion kernels (memory-bound, ~60us total)
// ---------------------------------------------------------------------------
__global__ __launch_bounds__(256) void cvt_x_kernel(const float* __restrict__ x)
{
    size_t e = ((size_t)blockIdx.x * 256 + threadIdx.x) * 4;
    if (e >= (size_t)MQKV * DIMn) return;
    int m = (int)(e >> 10);
    int col = (int)(e & 1023);
    int b = m / NTOK, n = m - b * NTOK;
    float4 v = make_float4(0.f, 0.f, 0.f, 0.f);
    if (n < NREAL) v = *(const float4*)(x + ((size_t)b * NREAL + n) * DIMn + col);
    __half2 h0 = __floats2half2_rn(v.x, v.y);
    __half2 h1 = __floats2half2_rn(v.z, v.w);
    uint2 u;
    u.x = *(unsigned*)&h0;
    u.y = *(unsigned*)&h1;
    *(uint2*)(g_xh + e) = u;
}

__global__ __launch_bounds__(256) void cvt_w_kernel(const float* __restrict__ w,
                                                    int nElem, int which)
{
    size_t e = ((size_t)blockIdx.x * 256 + threadIdx.x) * 4;
    if (e >= (size_t)nElem) return;
    __half* dst = which ? g_wouth : g_wqkvh;
    float4 v = *(const float4*)(w + e);
    __half2 h0 = __floats2half2_rn(v.x, v.y);
    __half2 h1 = __floats2half2_rn(v.z, v.w);
    uint2 u;
    u.x = *(unsigned*)&h0;
    u.y = *(unsigned*)&h1;
    *(uint2*)(dst + e) = u;
}

// g_o (plane layout fp32) -> g_oh [b*NREAL+n][h*64+d] fp16
__global__ __launch_bounds__(256) void cvt_o_kernel()
{
    size_t e = ((size_t)blockIdx.x * 256 + threadIdx.x) * 4;
    if (e >= (size_t)MOUT * DIMn) return;
    int m = (int)(e >> 10);
    int k = (int)(e & 1023);
    int b = m / NREAL, n = m - b * NREAL;
    int h = k >> 6, d = k & 63;
    float4 v = *(const float4*)(g_o + ((size_t)(b * Hn + h) * NTOK + n) * DHn + d);
    __half2 h0 = __floats2half2_rn(v.x, v.y);
    __half2 h1 = __floats2half2_rn(v.z, v.w);
    uint2 u;
    u.x = *(unsigned*)&h0;
    u.y = *(unsigned*)&h1;
    *(uint2*)(g_oh + e) = u;
}

// ---------------------------------------------------------------------------
// Attention (fp32, unchanged from R2): one block = 32 queries of one head.
// ---------------------------------------------------------------------------
__global__ __launch_bounds__(256) void text_attn_kernel()
{
    extern __shared__ float sm[];
    float* Qs = sm + SM_QS;
    float* KV = sm + SM_KV;
    float* S  = sm + SM_S;

    const int bh = blockIdx.y;
    const int q0 = blockIdx.x * 32;
    const int tid = threadIdx.x;
    const float* qbase = g_q + (size_t)bh * HD;
    const float* kbase = g_k + (size_t)bh * HD;
    const float* vbase = g_v + (size_t)bh * HD;

#pragma unroll
    for (int r = 0; r < 2; r++) {
        int idx = tid + 256 * r;
        int row = idx >> 4;
        int c4 = (idx & 15) * 4;
        *(float4*)&Qs[row * QS_STRIDE + c4] =
            *(const float4*)(qbase + (size_t)(q0 + row) * DHn + c4);
    }

    const int nkeys = q0 + 32;
    const int ntiles = (nkeys + 63) >> 6;
    const int qq = tid >> 3;
    const int l8 = tid & 7;
    const int qglob = q0 + qq;

    for (int kt = 0; kt < ntiles; kt++) {
        const int j0 = kt * 64;
        const int cnt = min(64, nkeys - j0);
        __syncthreads();
#pragma unroll
        for (int r = 0; r < 4; r++) {
            int idx = tid + 256 * r;
            int row = idx >> 4;
            int c4 = (idx & 15) * 4;
            if (row < cnt)
                *(float4*)&KV[row * QS_STRIDE + c4] =
                    *(const float4*)(kbase + (size_t)(j0 + row) * DHn + c4);
        }
        __syncthreads();
        float s[8] = {0, 0, 0, 0, 0, 0, 0, 0};
#pragma unroll 16
        for (int d = 0; d < 64; d++) {
            float qv = Qs[qq * QS_STRIDE + d];
#pragma unroll
            for (int jj = 0; jj < 8; jj++)
                s[jj] += qv * KV[(l8 + jj * 8) * QS_STRIDE + d];
        }
#pragma unroll
        for (int jj = 0; jj < 8; jj++) {
            int key = j0 + l8 + jj * 8;
            if (key < nkeys)
                S[qq * S_STRIDE + key] = (key <= qglob) ? s[jj] : -FLT_MAX;
        }
    }
    __syncthreads();

    float mx = -FLT_MAX;
    for (int j = l8; j < nkeys; j += 8) mx = fmaxf(mx, S[qq * S_STRIDE + j]);
#pragma unroll
    for (int o = 4; o; o >>= 1) mx = fmaxf(mx, __shfl_xor_sync(0xffffffffu, mx, o, 8));
    float sum = 0.f;
    for (int j = l8; j < nkeys; j += 8) {
        float e = __expf(S[qq * S_STRIDE + j] - mx);
        S[qq * S_STRIDE + j] = e;
        sum += e;
    }
#pragma unroll
    for (int o = 4; o; o >>= 1) sum += __shfl_xor_sync(0xffffffffu, sum, o, 8);
    const float inv = 1.0f / sum;

    float acc[8] = {0, 0, 0, 0, 0, 0, 0, 0};
    for (int kt = 0; kt < ntiles; kt++) {
        const int j0 = kt * 64;
        const int cnt = min(64, nkeys - j0);
        __syncthreads();
#pragma unroll
        for (int r = 0; r < 4; r++) {
            int idx = tid + 256 * r;
            int row = idx >> 4;
            int c4 = (idx & 15) * 4;
            if (row < cnt)
                *(float4*)&KV[row * QS_STRIDE + c4] =
                    *(const float4*)(vbase + (size_t)(j0 + row) * DHn + c4);
        }
        __syncthreads();
        for (int j = 0; j < cnt; j++) {
            float sv = S[qq * S_STRIDE + j0 + j];
#pragma unroll
            for (int dd = 0; dd < 8; dd++)
                acc[dd] += sv * KV[j * QS_STRIDE + l8 + dd * 8];
        }
    }
    float* obase = g_o + (size_t)bh * HD + (size_t)(q0 + qq) * DHn;
#pragma unroll
    for (int dd = 0; dd < 8; dd++) obase[l8 + dd * 8] = acc[dd] * inv;
}

__global__ __launch_bounds__(256) void img_attn_kernel()
{
    extern __shared__ float sm[];
    float* Qs = sm + SM_QS;
    float* KV = sm + SM_KV;
    float* S  = sm + SM_S;

    const int bh = blockIdx.y;
    const int xr = blockIdx.x;
    const int qtok0 = TXT + xr * 32;
    const int tid = threadIdx.x;
    const float* qbase = g_q + (size_t)bh * HD;
    const float* kbase = g_k + (size_t)bh * HD;
    const float* vbase = g_v + (size_t)bh * HD;

#pragma unroll
    for (int r = 0; r < 2; r++) {
        int idx = tid + 256 * r;
        int row = idx >> 4;
        int c4 = (idx & 15) * 4;
        *(float4*)&Qs[row * QS_STRIDE + c4] =
            *(const float4*)(qbase + (size_t)(qtok0 + row) * DHn + c4);
    }

    const int qq = tid >> 3;
    const int l8 = tid & 7;
    const int ncols = TXT + 32;

    for (int kt = 0; kt < 5; kt++) {
        const bool imgTile = (kt == 4);
        const int cnt = imgTile ? 32 : 64;
        const int ktok0 = imgTile ? qtok0 : kt * 64;
        __syncthreads();
#pragma unroll
        for (int r = 0; r < 4; r++) {
            int idx = tid + 256 * r;
            int row = idx >> 4;
            int c4 = (idx & 15) * 4;
            if (row < cnt)
                *(float4*)&KV[row * QS_STRIDE + c4] =
                    *(const float4*)(kbase + (size_t)(ktok0 + row) * DHn + c4);
        }
        __syncthreads();
        float s[8] = {0, 0, 0, 0, 0, 0, 0, 0};
#pragma unroll 16
        for (int d = 0; d < 64; d++) {
            float qv = Qs[qq * QS_STRIDE + d];
#pragma unroll
            for (int jj = 0; jj < 8; jj++)
                s[jj] += qv * KV[(l8 + jj * 8) * QS_STRIDE + d];
        }
        if (!imgTile) {
#pragma unroll
            for (int jj = 0; jj < 8; jj++)
                S[qq * S_STRIDE + kt * 64 + l8 + jj * 8] = s[jj];
        } else {
#pragma unroll
            for (int jj = 0; jj < 4; jj++) {
                int j = l8 + jj * 8;
                S[qq * S_STRIDE + TXT + j] = (j <= qq) ? s[jj] : -FLT_MAX;
            }
        }
    }
    __syncthreads();

    float mx = -FLT_MAX;
    for (int j = l8; j < ncols; j += 8) mx = fmaxf(mx, S[qq * S_STRIDE + j]);
#pragma unroll
    for (int o = 4; o; o >>= 1) mx = fmaxf(mx, __shfl_xor_sync(0xffffffffu, mx, o, 8));
    float sum = 0.f;
    for (int j = l8; j < ncols; j += 8) {
        float e = __expf(S[qq * S_STRIDE + j] - mx);
        S[qq * S_STRIDE + j] = e;
        sum += e;
    }
#pragma unroll
    for (int o = 4; o; o >>= 1) sum += __shfl_xor_sync(0xffffffffu, sum, o, 8);
    const float inv = 1.0f / sum;

    float acc[8] = {0, 0, 0, 0, 0, 0, 0, 0};
    for (int kt = 0; kt < 5; kt++) {
        const bool imgTile = (kt == 4);
        const int cnt = imgTile ? 32 : 64;
        const int vtok0 = imgTile ? qtok0 : kt * 64;
        const int scol0 = imgTile ? TXT : kt * 64;
        __syncthreads();
#pragma unroll
        for (int r = 0; r < 4; r++) {
            int idx = tid + 256 * r;
            int row = idx >> 4;
            int c4 = (idx & 15) * 4;
            if (row < cnt)
                *(float4*)&KV[row * QS_STRIDE + c4] =
                    *(const float4*)(vbase + (size_t)(vtok0 + row) * DHn + c4);
        }
        __syncthreads();
        for (int j = 0; j < cnt; j++) {
            float sv = S[qq * S_STRIDE + scol0 + j];
#pragma unroll
            for (int dd = 0; dd < 8; dd++)
                acc[dd] += sv * KV[j * QS_STRIDE + l8 + dd * 8];
        }
    }
    float* obase = g_o + (size_t)bh * HD + (size_t)(qtok0 + qq) * DHn;
#pragma unroll
    for (int dd = 0; dd < 8; dd++) obase[l8 + dd * 8] = acc[dd] * inv;
}

// ---------------------------------------------------------------------------
// Launch
// ---------------------------------------------------------------------------
extern "C" void kernel_launch(void* const* d_in, const int* in_sizes, int n_in,
                              void* d_out, int out_size)
{
    (void)in_sizes; (void)n_in; (void)out_size;
    const float* x     = (const float*)d_in[0];
    const float* w_qkv = (const float*)d_in[1];
    const float* w_out = (const float*)d_in[2];
    const float* b_out = (const float*)d_in[3];
    float* out = (float*)d_out;

    cudaFuncSetAttribute(text_attn_kernel,
                         cudaFuncAttributeMaxDynamicSharedMemorySize, SMEM_ATTN_BYTES);
    cudaFuncSetAttribute(img_attn_kernel,
                         cudaFuncAttributeMaxDynamicSharedMemorySize, SMEM_ATTN_BYTES);

    __half* xh_ptr = nullptr;   // device symbol pointers resolved inside kernels
    (void)xh_ptr;

    // 0) fp32 -> fp16 conversions of GEMM operands
    cvt_x_kernel<<<(MQKV * DIMn / 4 + 255) / 256, 256>>>(x);
    cvt_w_kernel<<<(3 * DIMn * DIMn / 4 + 255) / 256, 256>>>(w_qkv, 3 * DIMn * DIMn, 0);
    cvt_w_kernel<<<(DIMn * DIMn / 4 + 255) / 256, 256>>>(w_out, DIMn * DIMn, 1);

    // device-symbol addresses for template kernels
    void* p_xh;    cudaGetSymbolAddress(&p_xh, g_xh);
    void* p_wqkv;  cudaGetSymbolAddress(&p_wqkv, g_wqkvh);
    void* p_wout;  cudaGetSymbolAddress(&p_wout, g_wouth);
    void* p_oh;    cudaGetSymbolAddress(&p_oh, g_oh);

    // 1) QKV projection (fp16 tensor cores) into head-layout fp32 scratch
    hgemm_kernel<0><<<dim3(24, 160), 256>>>(
        (const __half*)p_xh, (const __half*)p_wqkv, nullptr, nullptr, MQKV);

    // 2) text causal attention (tokens 0..255)
    text_attn_kernel<<<dim3(8, 256), 256, SMEM_ATTN_BYTES>>>();
    // 3) axial image attention (tokens 256..1279)
    img_attn_kernel<<<dim3(32, 256), 256, SMEM_ATTN_BYTES>>>();

    // 4) de-interleave + convert attention output to fp16
    cvt_o_kernel<<<(MOUT * DIMn / 4 + 255) / 256, 256>>>();

    // 5) output projection + bias (fp16 tensor cores)
    hgemm_kernel<1><<<dim3(8, 160), 256>>>(
        (const __half*)p_oh, (const __half*)p_wout, b_out, out, MOUT);
}

// round 4
// speedup vs baseline: 6.0458x; 2.4422x over previous
#include <cuda_runtime.h>
#include <cuda_fp16.h>
#include <float.h>

// ---------------------------------------------------------------------------
// Problem constants
// ---------------------------------------------------------------------------
#define Bn     16
#define Hn     16
#define DHn    64
#define NTOK   1280          // padded sequence (SEQ_LEN + 1)
#define NREAL  1279          // real tokens
#define DIMn   1024
#define TXT    256           // text length
#define BH     256           // Bn * Hn
#define HD     (NTOK * DHn)  // 81920 halfs per (b,h) plane
#define MQKV   (Bn * NTOK)   // 20480
#define MOUT   (Bn * NREAL)  // 20464
#define QSCALE 0.125f        // DH^-0.5

// ---------------------------------------------------------------------------
// Scratch (device globals: allocation-free)
// ---------------------------------------------------------------------------
__device__ __half g_qh[(size_t)BH * HD];
__device__ __half g_kh[(size_t)BH * HD];
__device__ __half g_vh[(size_t)BH * HD];
__device__ __half g_xh[(size_t)MQKV * DIMn];     // padded x in fp16
__device__ __half g_wqkvh[3 * DIMn * DIMn];      // w_qkv fp16
__device__ __half g_wouth[DIMn * DIMn];          // w_out fp16
__device__ __half g_oh[(size_t)MOUT * DIMn];     // attn out, de-interleaved fp16

// ---------------------------------------------------------------------------
// MMA / ldmatrix helpers
// ---------------------------------------------------------------------------
__device__ __forceinline__ void mma_f16(float c[4], const unsigned a[4],
                                        const unsigned b[2]) {
    asm volatile(
        "mma.sync.aligned.m16n8k16.row.col.f32.f16.f16.f32 "
        "{%0,%1,%2,%3}, {%4,%5,%6,%7}, {%8,%9}, {%0,%1,%2,%3};\n"
        : "+f"(c[0]), "+f"(c[1]), "+f"(c[2]), "+f"(c[3])
        : "r"(a[0]), "r"(a[1]), "r"(a[2]), "r"(a[3]), "r"(b[0]), "r"(b[1]));
}

__device__ __forceinline__ void ldsm4(unsigned& r0, unsigned& r1,
                                      unsigned& r2, unsigned& r3, unsigned addr) {
    asm volatile("ldmatrix.sync.aligned.m8n8.x4.shared.b16 {%0,%1,%2,%3}, [%4];\n"
                 : "=r"(r0), "=r"(r1), "=r"(r2), "=r"(r3) : "r"(addr));
}

__device__ __forceinline__ void ldsm4t(unsigned& r0, unsigned& r1,
                                       unsigned& r2, unsigned& r3, unsigned addr) {
    asm volatile("ldmatrix.sync.aligned.m8n8.x4.trans.shared.b16 {%0,%1,%2,%3}, [%4];\n"
                 : "=r"(r0), "=r"(r1), "=r"(r2), "=r"(r3) : "r"(addr));
}

// GEMM smem swizzle: 64B rows (32 halfs), chunk c (0..3)
__device__ __forceinline__ unsigned swz(int row, int c) {
    return (unsigned)(row * 64 + ((c ^ ((row >> 1) & 3)) << 4));
}
// Attention tiles: 128B rows (64 halfs), chunk c (0..7)
__device__ __forceinline__ unsigned off16(int row, int c) {
    return (unsigned)(row * 128 + ((c ^ (row & 7)) << 4));
}
// Score matrix S: 640B rows (320 halfs), chunk c (0..39), swizzle within 8-chunk groups
__device__ __forceinline__ unsigned sidx16(int row, int c) {
    int cc = (c & ~7) | ((c & 7) ^ (row & 7));
    return (unsigned)(row * 640 + (cc << 4));
}
__device__ __forceinline__ char* sptr(char* base, int row, int col) {
    return base + sidx16(row, col >> 3) + (col & 7) * 2;
}

__device__ __forceinline__ void cp16(unsigned dst, const void* src, bool v) {
    int sz = v ? 16 : 0;
    asm volatile("cp.async.cg.shared.global [%0], [%1], 16, %2;\n"
                 :: "r"(dst), "l"(src), "r"(sz) : "memory");
}
__device__ __forceinline__ void cp_commit() {
    asm volatile("cp.async.commit_group;\n" ::: "memory");
}
__device__ __forceinline__ void cp_wait1() {
    asm volatile("cp.async.wait_group 1;\n" ::: "memory");
}

// ---------------------------------------------------------------------------
// fp16 HGEMM, C[m,n] = sum_k A[m,k]*B[n,k]. 128x128x32, 3-stage cp.async.
// EPI=0: scatter fp16 to g_qh/g_kh/g_vh head layout (Q scaled).
// EPI=1: fp32 out + bias.
// ---------------------------------------------------------------------------
template <int EPI>
__global__ __launch_bounds__(256, 2) void hgemm_kernel(
    const __half* __restrict__ A, const __half* __restrict__ B,
    const float* __restrict__ bias, float* __restrict__ out, int Mv)
{
    __shared__ __align__(16) __half smem[3 * 2 * 128 * 32];  // 49152 B
    const unsigned smbase = (unsigned)__cvta_generic_to_shared(smem);

    const int tid = threadIdx.x;
    const int m0 = blockIdx.y * 128;
    const int n0 = blockIdx.x * 128;

    const int lr = tid >> 1;
    const int lc = (tid & 1) * 2;
    const __half* gA = A + (size_t)(m0 + lr) * DIMn + lc * 8;
    const __half* gB = B + (size_t)(n0 + lr) * DIMn + lc * 8;
    const bool av = (m0 + lr) < Mv;
    const unsigned dA0 = swz(lr, lc), dA1 = swz(lr, lc + 1);

    auto load_stage = [&](int s, int k0) {
        unsigned sb = smbase + s * 16384;
        const __half* pa = gA + k0;
        const __half* pb = gB + k0;
        cp16(sb + dA0, pa, av);
        cp16(sb + dA1, pa + 8, av);
        cp16(sb + 8192 + dA0, pb, true);
        cp16(sb + 8192 + dA1, pb + 8, true);
    };

    const int lane = tid & 31, warp = tid >> 5;
    const int wM = warp >> 1, wN = warp & 1;
    const int aRow = wM * 32 + (lane & 15);
    const int aCb  = lane >> 4;
    const int bRow = wN * 64 + (lane & 7) + ((lane >> 4) & 1) * 8;
    const int bCb  = (lane >> 3) & 1;

    float c[2][8][4];
#pragma unroll
    for (int tm = 0; tm < 2; tm++)
#pragma unroll
        for (int tn = 0; tn < 8; tn++)
#pragma unroll
            for (int i = 0; i < 4; i++) c[tm][tn][i] = 0.f;

    load_stage(0, 0);  cp_commit();
    load_stage(1, 32); cp_commit();

    for (int it = 0; it < 32; it++) {
        cp_wait1();
        __syncthreads();
        if (it + 2 < 32) load_stage((it + 2) % 3, (it + 2) * 32);
        cp_commit();

        const unsigned sb = smbase + (it % 3) * 16384;
#pragma unroll
        for (int k16 = 0; k16 < 2; k16++) {
            unsigned a[2][4], b[4][4];
#pragma unroll
            for (int tm = 0; tm < 2; tm++)
                ldsm4(a[tm][0], a[tm][1], a[tm][2], a[tm][3],
                      sb + swz(aRow + tm * 16, aCb + 2 * k16));
#pragma unroll
            for (int p = 0; p < 4; p++)
                ldsm4(b[p][0], b[p][1], b[p][2], b[p][3],
                      sb + 8192 + swz(bRow + p * 16, bCb + 2 * k16));
#pragma unroll
            for (int tm = 0; tm < 2; tm++)
#pragma unroll
                for (int tn = 0; tn < 8; tn++)
                    mma_f16(c[tm][tn], a[tm], &b[tn >> 1][(tn & 1) * 2]);
        }
    }

    const int grp = lane >> 2, qd = lane & 3;
#pragma unroll
    for (int tm = 0; tm < 2; tm++) {
#pragma unroll
        for (int hf = 0; hf < 2; hf++) {
            const int mrow = m0 + wM * 32 + tm * 16 + grp + hf * 8;
            if (EPI == 0) {
                const int b_ = mrow / NTOK;
                const int n_ = mrow - b_ * NTOK;
#pragma unroll
                for (int tn = 0; tn < 8; tn++) {
                    const int col = n0 + wN * 64 + tn * 8 + qd * 2;
                    const int which = col >> 10;
                    const int cc = col & 1023;
                    const int h = cc >> 6;
                    const int d = cc & 63;
                    __half* dst = (which == 0) ? g_qh : ((which == 1) ? g_kh : g_vh);
                    const float sc = (which == 0) ? QSCALE : 1.0f;
                    __half2 hv = __floats2half2_rn(c[tm][tn][hf * 2 + 0] * sc,
                                                   c[tm][tn][hf * 2 + 1] * sc);
                    *(unsigned*)(dst + ((size_t)(b_ * Hn + h) * NTOK + n_) * DHn + d) =
                        *(unsigned*)&hv;
                }
            } else {
                if (mrow < Mv) {
#pragma unroll
                    for (int tn = 0; tn < 8; tn++) {
                        const int col = n0 + wN * 64 + tn * 8 + qd * 2;
                        float2 bb = *(const float2*)(bias + col);
                        float2 v;
                        v.x = c[tm][tn][hf * 2 + 0] + bb.x;
                        v.y = c[tm][tn][hf * 2 + 1] + bb.y;
                        *(float2*)(out + (size_t)mrow * DIMn + col) = v;
                    }
                }
            }
        }
    }
}

// ---------------------------------------------------------------------------
// fp32 -> fp16 conversion kernels
// ---------------------------------------------------------------------------
__global__ __launch_bounds__(256) void cvt_x_kernel(const float* __restrict__ x)
{
    size_t e = ((size_t)blockIdx.x * 256 + threadIdx.x) * 4;
    if (e >= (size_t)MQKV * DIMn) return;
    int m = (int)(e >> 10);
    int col = (int)(e & 1023);
    int b = m / NTOK, n = m - b * NTOK;
    float4 v = make_float4(0.f, 0.f, 0.f, 0.f);
    if (n < NREAL) v = *(const float4*)(x + ((size_t)b * NREAL + n) * DIMn + col);
    __half2 h0 = __floats2half2_rn(v.x, v.y);
    __half2 h1 = __floats2half2_rn(v.z, v.w);
    uint2 u;
    u.x = *(unsigned*)&h0;
    u.y = *(unsigned*)&h1;
    *(uint2*)(g_xh + e) = u;
}

__global__ __launch_bounds__(256) void cvt_w_kernel(const float* __restrict__ w,
                                                    int nElem, int which)
{
    size_t e = ((size_t)blockIdx.x * 256 + threadIdx.x) * 4;
    if (e >= (size_t)nElem) return;
    __half* dst = which ? g_wouth : g_wqkvh;
    float4 v = *(const float4*)(w + e);
    __half2 h0 = __floats2half2_rn(v.x, v.y);
    __half2 h1 = __floats2half2_rn(v.z, v.w);
    uint2 u;
    u.x = *(unsigned*)&h0;
    u.y = *(unsigned*)&h1;
    *(uint2*)(dst + e) = u;
}

// ---------------------------------------------------------------------------
// Tensor-core attention.
// Shared smem layout (dynamic, 65792 B):
//   Q  [64][64] fp16 swizzled (off16)          @ 0      (8192 B)
//   K  [64][64] fp16 swizzled                  @ 8192   (8192 B)
//   V  [64][64] fp16 swizzled                  @ 16384  (8192 B)
//   S  [64][320] fp16 swizzled (sidx16)        @ 24576  (40960 B)
//   inv[64] fp32                               @ 65536  (256 B)
// Block = 128 threads (4 warps), each warp owns 16 query rows.
// ---------------------------------------------------------------------------
#define ATT_QOFF 0
#define ATT_KOFF 8192
#define ATT_VOFF 16384
#define ATT_SOFF 24576
#define ATT_IOFF 65536
#define ATT_SMEM 65792

__device__ __forceinline__ void att_load_tile(char* sm, unsigned off,
                                              const __half* g, int tid) {
#pragma unroll
    for (int r = 0; r < 4; r++) {
        int id = tid + 128 * r;
        int row = id >> 3, c = id & 7;
        *(uint4*)(sm + off + off16(row, c)) = *(const uint4*)(g + row * 64 + c * 8);
    }
}

// Text attention: 64 queries per block, causal over nkeys = q0+64.
__global__ __launch_bounds__(128) void text_attn_kernel()
{
    extern __shared__ char sm[];
    const unsigned sb = (unsigned)__cvta_generic_to_shared(sm);
    float* invs = (float*)(sm + ATT_IOFF);

    const int bh = blockIdx.y, bx = blockIdx.x;
    const int q0 = bx * 64;
    const int tid = threadIdx.x, lane = tid & 31, warp = tid >> 5;
    const int grp = lane >> 2, qd = lane & 3;

    const __half* qg = g_qh + (size_t)bh * HD + (size_t)q0 * DHn;
    const __half* kg = g_kh + (size_t)bh * HD;
    const __half* vg = g_vh + (size_t)bh * HD;

    att_load_tile(sm, ATT_QOFF, qg, tid);

    const int aRow = warp * 16 + (lane & 15);
    const int aC   = lane >> 4;
    const int bRow = (lane & 7) + ((lane >> 4) & 1) * 8;
    const int bC   = (lane >> 3) & 1;

    // ---- scores ----
    for (int kt = 0; kt <= bx; kt++) {
        const int j0 = kt * 64;
        __syncthreads();
        att_load_tile(sm, ATT_KOFF, kg + (size_t)j0 * DHn, tid);
        __syncthreads();

        float cs[8][4];
#pragma unroll
        for (int tn = 0; tn < 8; tn++)
#pragma unroll
            for (int i = 0; i < 4; i++) cs[tn][i] = 0.f;

#pragma unroll
        for (int k16 = 0; k16 < 4; k16++) {
            unsigned a[4], b[4][4];
            ldsm4(a[0], a[1], a[2], a[3],
                  sb + ATT_QOFF + off16(aRow, k16 * 2 + aC));
#pragma unroll
            for (int p = 0; p < 4; p++)
                ldsm4(b[p][0], b[p][1], b[p][2], b[p][3],
                      sb + ATT_KOFF + off16(p * 16 + bRow, k16 * 2 + bC));
#pragma unroll
            for (int tn = 0; tn < 8; tn++)
                mma_f16(cs[tn], a, &b[tn >> 1][(tn & 1) * 2]);
        }
        const bool diag = (kt == bx);
#pragma unroll
        for (int tn = 0; tn < 8; tn++) {
#pragma unroll
            for (int hf = 0; hf < 2; hf++) {
                const int row = warp * 16 + grp + hf * 8;
                const int col = j0 + tn * 8 + qd * 2;
                float v0 = cs[tn][hf * 2 + 0];
                float v1 = cs[tn][hf * 2 + 1];
                if (diag) {
                    const int qglob = q0 + row;
                    if (col > qglob)     v0 = -1e30f;
                    if (col + 1 > qglob) v1 = -1e30f;
                }
                __half2 h = __floats2half2_rn(v0, v1);
                *(unsigned*)sptr(sm + ATT_SOFF, row, col) = *(unsigned*)&h;
            }
        }
    }
    __syncthreads();

    // ---- softmax (2 threads per row) ----
    {
        const int nkeys = q0 + 64;
        const int row = tid >> 1, hv = tid & 1;
        const int c0 = hv * (nkeys >> 1), c1 = c0 + (nkeys >> 1);
        float mx = -FLT_MAX;
        for (int col = c0; col < c1; col++)
            mx = fmaxf(mx, __half2float(*(__half*)sptr(sm + ATT_SOFF, row, col)));
        mx = fmaxf(mx, __shfl_xor_sync(0xffffffffu, mx, 1));
        float sum = 0.f;
        for (int col = c0; col < c1; col++) {
            char* p = sptr(sm + ATT_SOFF, row, col);
            float e = __expf(__half2float(*(__half*)p) - mx);
            *(__half*)p = __float2half(e);
            sum += e;
        }
        sum += __shfl_xor_sync(0xffffffffu, sum, 1);
        if (hv == 0) invs[row] = 1.f / sum;
    }
    __syncthreads();

    // ---- AV ----
    float co[8][4];
#pragma unroll
    for (int tn = 0; tn < 8; tn++)
#pragma unroll
        for (int i = 0; i < 4; i++) co[tn][i] = 0.f;

    for (int kt = 0; kt <= bx; kt++) {
        const int j0 = kt * 64;
        __syncthreads();
        att_load_tile(sm, ATT_VOFF, vg + (size_t)j0 * DHn, tid);
        __syncthreads();
#pragma unroll
        for (int k16 = 0; k16 < 4; k16++) {
            unsigned a[4], b[4][4];
            ldsm4(a[0], a[1], a[2], a[3],
                  sb + ATT_SOFF + sidx16(aRow, (j0 >> 3) + k16 * 2 + aC));
#pragma unroll
            for (int n16 = 0; n16 < 4; n16++)
                ldsm4t(b[n16][0], b[n16][1], b[n16][2], b[n16][3],
                       sb + ATT_VOFF + off16(k16 * 16 + (lane & 15),
                                             n16 * 2 + (lane >> 4)));
#pragma unroll
            for (int tn = 0; tn < 8; tn++)
                mma_f16(co[tn], a, &b[tn >> 1][(tn & 1) * 2]);
        }
    }

    const float inv0 = invs[warp * 16 + grp];
    const float inv1 = invs[warp * 16 + grp + 8];
    const int b_ = bh >> 4, h_ = bh & 15;
#pragma unroll
    for (int tn = 0; tn < 8; tn++) {
#pragma unroll
        for (int hf = 0; hf < 2; hf++) {
            const int row = warp * 16 + grp + hf * 8;
            const int token = q0 + row;
            const int m = b_ * NREAL + token;
            const int col = h_ * 64 + tn * 8 + qd * 2;
            const float inv = hf ? inv1 : inv0;
            __half2 h = __floats2half2_rn(co[tn][hf * 2 + 0] * inv,
                                          co[tn][hf * 2 + 1] * inv);
            *(unsigned*)(g_oh + (size_t)m * DIMn + col) = *(unsigned*)&h;
        }
    }
}

// Image attention: block = (rowpair rp, bh). 64 contiguous query tokens
// (two image rows). Keys: 256 text (unmasked) + 32 same-row image (causal).
__global__ __launch_bounds__(128) void img_attn_kernel()
{
    extern __shared__ char sm[];
    const unsigned sb = (unsigned)__cvta_generic_to_shared(sm);
    float* invs = (float*)(sm + ATT_IOFF);

    const int bh = blockIdx.y, rp = blockIdx.x;
    const int qbase = TXT + rp * 64;
    const int tid = threadIdx.x, lane = tid & 31, warp = tid >> 5;
    const int grp = lane >> 2, qd = lane & 3;

    const __half* qg = g_qh + (size_t)bh * HD + (size_t)qbase * DHn;
    const __half* kg = g_kh + (size_t)bh * HD;
    const __half* vg = g_vh + (size_t)bh * HD;

    att_load_tile(sm, ATT_QOFF, qg, tid);

    const int aRow = warp * 16 + (lane & 15);
    const int aC   = lane >> 4;
    const int bRow = (lane & 7) + ((lane >> 4) & 1) * 8;
    const int bC   = (lane >> 3) & 1;
    const int kb   = (warp >> 1) * 32;   // per-warp image K/V base row

    // ---- text scores (no mask) ----
    for (int kt = 0; kt < 4; kt++) {
        const int j0 = kt * 64;
        __syncthreads();
        att_load_tile(sm, ATT_KOFF, kg + (size_t)j0 * DHn, tid);
        __syncthreads();

        float cs[8][4];
#pragma unroll
        for (int tn = 0; tn < 8; tn++)
#pragma unroll
            for (int i = 0; i < 4; i++) cs[tn][i] = 0.f;

#pragma unroll
        for (int k16 = 0; k16 < 4; k16++) {
            unsigned a[4], b[4][4];
            ldsm4(a[0], a[1], a[2], a[3],
                  sb + ATT_QOFF + off16(aRow, k16 * 2 + aC));
#pragma unroll
            for (int p = 0; p < 4; p++)
                ldsm4(b[p][0], b[p][1], b[p][2], b[p][3],
                      sb + ATT_KOFF + off16(p * 16 + bRow, k16 * 2 + bC));
#pragma unroll
            for (int tn = 0; tn < 8; tn++)
                mma_f16(cs[tn], a, &b[tn >> 1][(tn & 1) * 2]);
        }
#pragma unroll
        for (int tn = 0; tn < 8; tn++) {
#pragma unroll
            for (int hf = 0; hf < 2; hf++) {
                const int row = warp * 16 + grp + hf * 8;
                const int col = j0 + tn * 8 + qd * 2;
                __half2 h = __floats2half2_rn(cs[tn][hf * 2 + 0],
                                              cs[tn][hf * 2 + 1]);
                *(unsigned*)sptr(sm + ATT_SOFF, row, col) = *(unsigned*)&h;
            }
        }
    }

    // ---- image scores (causal within row) ----
    {
        __syncthreads();
        att_load_tile(sm, ATT_KOFF, kg + (size_t)qbase * DHn, tid);  // K of query tokens
        __syncthreads();

        float cs[4][4];
#pragma unroll
        for (int tn = 0; tn < 4; tn++)
#pragma unroll
            for (int i = 0; i < 4; i++) cs[tn][i] = 0.f;

#pragma unroll
        for (int k16 = 0; k16 < 4; k16++) {
            unsigned a[4], b[2][4];
            ldsm4(a[0], a[1], a[2], a[3],
                  sb + ATT_QOFF + off16(aRow, k16 * 2 + aC));
#pragma unroll
            for (int p = 0; p < 2; p++)
                ldsm4(b[p][0], b[p][1], b[p][2], b[p][3],
                      sb + ATT_KOFF + off16(kb + p * 16 + bRow, k16 * 2 + bC));
#pragma unroll
            for (int tn = 0; tn < 4; tn++)
                mma_f16(cs[tn], a, &b[tn >> 1][(tn & 1) * 2]);
        }
#pragma unroll
        for (int tn = 0; tn < 4; tn++) {
#pragma unroll
            for (int hf = 0; hf < 2; hf++) {
                const int row = warp * 16 + grp + hf * 8;
                const int qlocal = row & 31;
                const int j = tn * 8 + qd * 2;
                float v0 = (j     <= qlocal) ? cs[tn][hf * 2 + 0] : -1e30f;
                float v1 = (j + 1 <= qlocal) ? cs[tn][hf * 2 + 1] : -1e30f;
                __half2 h = __floats2half2_rn(v0, v1);
                *(unsigned*)sptr(sm + ATT_SOFF, row, TXT + j) = *(unsigned*)&h;
            }
        }
    }
    __syncthreads();

    // ---- softmax over 288 cols ----
    {
        const int row = tid >> 1, hv = tid & 1;
        const int c0 = hv * 144, c1 = c0 + 144;
        float mx = -FLT_MAX;
        for (int col = c0; col < c1; col++)
            mx = fmaxf(mx, __half2float(*(__half*)sptr(sm + ATT_SOFF, row, col)));
        mx = fmaxf(mx, __shfl_xor_sync(0xffffffffu, mx, 1));
        float sum = 0.f;
        for (int col = c0; col < c1; col++) {
            char* p = sptr(sm + ATT_SOFF, row, col);
            float e = __expf(__half2float(*(__half*)p) - mx);
            *(__half*)p = __float2half(e);
            sum += e;
        }
        sum += __shfl_xor_sync(0xffffffffu, sum, 1);
        if (hv == 0) invs[row] = 1.f / sum;
    }
    __syncthreads();

    // ---- AV ----
    float co[8][4];
#pragma unroll
    for (int tn = 0; tn < 8; tn++)
#pragma unroll
        for (int i = 0; i < 4; i++) co[tn][i] = 0.f;

    for (int kt = 0; kt < 4; kt++) {           // text V tiles
        const int j0 = kt * 64;
        __syncthreads();
        att_load_tile(sm, ATT_VOFF, vg + (size_t)j0 * DHn, tid);
        __syncthreads();
#pragma unroll
        for (int k16 = 0; k16 < 4; k16++) {
            unsigned a[4], b[4][4];
            ldsm4(a[0], a[1], a[2], a[3],
                  sb + ATT_SOFF + sidx16(aRow, (j0 >> 3) + k16 * 2 + aC));
#pragma unroll
            for (int n16 = 0; n16 < 4; n16++)
                ldsm4t(b[n16][0], b[n16][1], b[n16][2], b[n16][3],
                       sb + ATT_VOFF + off16(k16 * 16 + (lane & 15),
                                             n16 * 2 + (lane >> 4)));
#pragma unroll
            for (int tn = 0; tn < 8; tn++)
                mma_f16(co[tn], a, &b[tn >> 1][(tn & 1) * 2]);
        }
    }
    {   // image V tile (row-specific per warp)
        __syncthreads();
        att_load_tile(sm, ATT_VOFF, vg + (size_t)qbase * DHn, tid);
        __syncthreads();
#pragma unroll
        for (int k16 = 0; k16 < 2; k16++) {
            unsigned a[4], b[4][4];
            ldsm4(a[0], a[1], a[2], a[3],
                  sb + ATT_SOFF + sidx16(aRow, (TXT >> 3) + k16 * 2 + aC));
#pragma unroll
            for (int n16 = 0; n16 < 4; n16++)
                ldsm4t(b[n16][0], b[n16][1], b[n16][2], b[n16][3],
                       sb + ATT_VOFF + off16(kb + k16 * 16 + (lane & 15),
                                             n16 * 2 + (lane >> 4)));
#pragma unroll
            for (int tn = 0; tn < 8; tn++)
                mma_f16(co[tn], a, &b[tn >> 1][(tn & 1) * 2]);
        }
    }

    const float inv0 = invs[warp * 16 + grp];
    const float inv1 = invs[warp * 16 + grp + 8];
    const int b_ = bh >> 4, h_ = bh & 15;
#pragma unroll
    for (int tn = 0; tn < 8; tn++) {
#pragma unroll
        for (int hf = 0; hf < 2; hf++) {
            const int row = warp * 16 + grp + hf * 8;
            const int token = qbase + row;
            if (token >= NREAL) continue;      // padded token 1279
            const int m = b_ * NREAL + token;
            const int col = h_ * 64 + tn * 8 + qd * 2;
            const float inv = hf ? inv1 : inv0;
            __half2 h = __floats2half2_rn(co[tn][hf * 2 + 0] * inv,
                                          co[tn][hf * 2 + 1] * inv);
            *(unsigned*)(g_oh + (size_t)m * DIMn + col) = *(unsigned*)&h;
        }
    }
}

// ---------------------------------------------------------------------------
// Launch
// ---------------------------------------------------------------------------
extern "C" void kernel_launch(void* const* d_in, const int* in_sizes, int n_in,
                              void* d_out, int out_size)
{
    (void)in_sizes; (void)n_in; (void)out_size;
    const float* x     = (const float*)d_in[0];
    const float* w_qkv = (const float*)d_in[1];
    const float* w_out = (const float*)d_in[2];
    const float* b_out = (const float*)d_in[3];
    float* out = (float*)d_out;

    cudaFuncSetAttribute(text_attn_kernel,
                         cudaFuncAttributeMaxDynamicSharedMemorySize, ATT_SMEM);
    cudaFuncSetAttribute(img_attn_kernel,
                         cudaFuncAttributeMaxDynamicSharedMemorySize, ATT_SMEM);

    // 0) fp32 -> fp16 conversions of GEMM operands
    cvt_x_kernel<<<(MQKV * DIMn / 4 + 255) / 256, 256>>>(x);
    cvt_w_kernel<<<(3 * DIMn * DIMn / 4 + 255) / 256, 256>>>(w_qkv, 3 * DIMn * DIMn, 0);
    cvt_w_kernel<<<(DIMn * DIMn / 4 + 255) / 256, 256>>>(w_out, DIMn * DIMn, 1);

    void* p_xh;    cudaGetSymbolAddress(&p_xh, g_xh);
    void* p_wqkv;  cudaGetSymbolAddress(&p_wqkv, g_wqkvh);
    void* p_wout;  cudaGetSymbolAddress(&p_wout, g_wouth);
    void* p_oh;    cudaGetSymbolAddress(&p_oh, g_oh);

    // 1) QKV projection (fp16 tensor cores) into fp16 head-layout scratch
    hgemm_kernel<0><<<dim3(24, 160), 256>>>(
        (const __half*)p_xh, (const __half*)p_wqkv, nullptr, nullptr, MQKV);

    // 2) text causal attention (tokens 0..255)
    text_attn_kernel<<<dim3(4, 256), 128, ATT_SMEM>>>();
    // 3) axial image attention (tokens 256..1279), 2 image rows per block
    img_attn_kernel<<<dim3(16, 256), 128, ATT_SMEM>>>();

    // 4) output projection + bias (fp16 tensor cores)
    hgemm_kernel<1><<<dim3(8, 160), 256>>>(
        (const __half*)p_oh, (const __half*)p_wout, b_out, out, MOUT);
}